// round 14
// baseline (speedup 1.0000x reference)
#include <cuda_runtime.h>

#define SH 48                 // rows per warp strip (H=384 -> 8 strips)
#define WPB 4                 // warps per block
#define NTHREADS (WPB * 32)
#define MAXB 8192

__device__ float2 g_part[MAXB];
__device__ unsigned int g_done = 0;   // self-resetting -> graph-replay safe

// Load one tensor-channel row into extended register row e[6]:
// e[0]=col-1, e[1..4]=own 4 cols, e[5]=col+4. pl = plane base + x0 + 4*lane.
__device__ __forceinline__ void load_tc(
    float (&e)[6], const float* __restrict__ pl, int ro,
    bool inr, bool lok, bool rok, int lane)
{
    float4 v = make_float4(0.f, 0.f, 0.f, 0.f);
    float lft = 0.f, rgt = 0.f;
    if (inr) {
        v = *(const float4*)(pl + ro);
        if (lane == 0 && lok)   lft = pl[ro - 1];   // col x0-1
        if (lane == 31 && rok)  rgt = pl[ro + 4];   // col x0+128
    }
    float e0 = __shfl_up_sync(0xFFFFFFFFu, v.w, 1);
    float e5 = __shfl_down_sync(0xFFFFFFFFu, v.x, 1);
    e[0] = (lane == 0)  ? lft : e0;
    e[5] = (lane == 31) ? rgt : e5;
    e[1] = v.x; e[2] = v.y; e[3] = v.z; e[4] = v.w;
}

#define LOADROW(R, gy_) do {                                          \
    const int  _gy = (gy_);                                           \
    const bool _in = (_gy >= 0) && (_gy < H);                         \
    const int  _ro = _gy * W;                                         \
    load_tc(R[0][0], pl00, _ro, _in, lok, rok, lane);                 \
    load_tc(R[0][1], pl01, _ro, _in, lok, rok, lane);                 \
    load_tc(R[0][2], pl02, _ro, _in, lok, rok, lane);                 \
    load_tc(R[1][0], pl10, _ro, _in, lok, rok, lane);                 \
    load_tc(R[1][1], pl11, _ro, _in, lok, rok, lane);                 \
    load_tc(R[1][2], pl12, _ro, _in, lok, rok, lane);                 \
} while (0)

// Scharr gradients + cross product + normalize for 4 px of one row.
// A = row above, B = row, C = row below. (Uniform 3x filter scale cancels.)
__device__ __forceinline__ void norm_row(
    const float (&A)[3][6], const float (&B)[3][6], const float (&C)[3][6],
    float (&n)[3][4])
{
    float GX[3][4], GY[3][4];
    #pragma unroll
    for (int ch = 0; ch < 3; ch++) {
        float cs[6], rd[6];
        #pragma unroll
        for (int j = 0; j < 6; j++) {
            cs[j] = A[ch][j] + B[ch][j] + C[ch][j];
            rd[j] = C[ch][j] - A[ch][j];
        }
        #pragma unroll
        for (int i = 0; i < 4; i++) {
            GX[ch][i] = cs[i + 2] - cs[i];
            GY[ch][i] = rd[i] + rd[i + 1] + rd[i + 2];
        }
    }
    #pragma unroll
    for (int i = 0; i < 4; i++) {
        float nx = GX[1][i] * GY[2][i] - GX[2][i] * GY[1][i];
        float ny = GX[2][i] * GY[0][i] - GX[0][i] * GY[2][i];
        float nz = GX[0][i] * GY[1][i] - GX[1][i] * GY[0][i];
        float inv = rsqrtf(nx * nx + ny * ny + nz * nz + 1e-20f);
        n[0][i] = nx * inv; n[1][i] = ny * inv; n[2][i] = nz * inv;
    }
}

__device__ __forceinline__ void do_row(
    const float (&P)[2][3][6], const float (&Cc)[2][3][6], const float (&N)[2][3][6],
    const float* __restrict__ mrowl, float& lsum, float& msum)
{
    float4 mv = *(const float4*)mrowl;
    float pn[3][4], gn[3][4];
    norm_row(P[0], Cc[0], N[0], pn);
    norm_row(P[1], Cc[1], N[1], gn);
    float mm[4] = {mv.x, mv.y, mv.z, mv.w};
    #pragma unroll
    for (int i = 0; i < 4; i++) {
        lsum += mm[i] * (fabsf(pn[0][i] - gn[0][i]) + fabsf(pn[1][i] - gn[1][i])
                       + fabsf(pn[2][i] - gn[2][i]));
        msum += mm[i];
    }
}

__global__ __launch_bounds__(NTHREADS) void normal_loss_kernel(
    const float* __restrict__ pred,
    const float* __restrict__ gt,
    const float* __restrict__ mask,
    float* __restrict__ out,
    int H, int W, int nblocks)
{
    __shared__ float  rl[WPB], rm[WPB];
    __shared__ double drl[WPB], drm[WPB];
    __shared__ int s_last;

    const int tid  = threadIdx.x;
    const int warp = tid >> 5;
    const int lane = tid & 31;

    const int b  = blockIdx.z;
    const int x0 = blockIdx.x * 128;
    const int sy = blockIdx.y * WPB + warp;
    const int y0 = sy * SH;

    const int plane = H * W;
    const float* pbase = pred + (size_t)b * 3 * plane;
    const float* gbase = gt   + (size_t)b * 3 * plane;

    const float* pl00 = pbase + 0 * plane + x0 + 4 * lane;
    const float* pl01 = pbase + 1 * plane + x0 + 4 * lane;
    const float* pl02 = pbase + 2 * plane + x0 + 4 * lane;
    const float* pl10 = gbase + 0 * plane + x0 + 4 * lane;
    const float* pl11 = gbase + 1 * plane + x0 + 4 * lane;
    const float* pl12 = gbase + 2 * plane + x0 + 4 * lane;
    const float* mpl  = mask + (size_t)b * plane + x0 + 4 * lane;

    const bool lok = (x0 > 0);
    const bool rok = (x0 + 128 < W);

    float RA[2][3][6], RB[2][3][6], RC[2][3][6];
    float lsum = 0.f, msum = 0.f;

    LOADROW(RA, y0 - 1);
    LOADROW(RB, y0);

    for (int k = 0; k < SH; k += 3) {
        LOADROW(RC, y0 + k + 1);
        do_row(RA, RB, RC, mpl + (y0 + k) * W, lsum, msum);
        LOADROW(RA, y0 + k + 2);
        do_row(RB, RC, RA, mpl + (y0 + k + 1) * W, lsum, msum);
        LOADROW(RB, y0 + k + 3);
        do_row(RC, RA, RB, mpl + (y0 + k + 2) * W, lsum, msum);
    }

    // ---- Warp reduce -> block reduce -> per-block partial ----
    #pragma unroll
    for (int o = 16; o > 0; o >>= 1) {
        lsum += __shfl_down_sync(0xFFFFFFFFu, lsum, o);
        msum += __shfl_down_sync(0xFFFFFFFFu, msum, o);
    }
    if (lane == 0) { rl[warp] = lsum; rm[warp] = msum; }
    __syncthreads();

    const int bid = (blockIdx.z * gridDim.y + blockIdx.y) * gridDim.x + blockIdx.x;
    if (tid == 0) {
        float tl = 0.f, tm = 0.f;
        #pragma unroll
        for (int w = 0; w < WPB; w++) { tl += rl[w]; tm += rm[w]; }
        g_part[bid] = make_float2(tl, tm);
        __threadfence();
        unsigned int old = atomicAdd(&g_done, 1u);
        s_last = (old == (unsigned)(nblocks - 1)) ? 1 : 0;
    }
    __syncthreads();

    // ---- Last block: final double-precision reduction + output + reset ----
    if (s_last) {
        double dl = 0.0, dm = 0.0;
        for (int i = tid; i < nblocks; i += NTHREADS) {
            float2 p = __ldcg(&g_part[i]);
            dl += (double)p.x; dm += (double)p.y;
        }
        #pragma unroll
        for (int o = 16; o > 0; o >>= 1) {
            dl += __shfl_down_sync(0xFFFFFFFFu, dl, o);
            dm += __shfl_down_sync(0xFFFFFFFFu, dm, o);
        }
        if (lane == 0) { drl[warp] = dl; drm[warp] = dm; }
        __syncthreads();
        if (tid == 0) {
            double tl = 0.0, tm = 0.0;
            #pragma unroll
            for (int w = 0; w < WPB; w++) { tl += drl[w]; tm += drm[w]; }
            out[0] = (float)(tl / tm);
            g_done = 0;   // restore for next graph replay
        }
    }
}

extern "C" void kernel_launch(void* const* d_in, const int* in_sizes, int n_in,
                              void* d_out, int out_size)
{
    const float* pred = (const float*)d_in[0];
    const float* gt   = (const float*)d_in[1];
    const float* mask = (const float*)d_in[2];
    float* out = (float*)d_out;

    const int H = 384;
    const int W = 1280;
    const int B = in_sizes[2] / (H * W);

    dim3 block(NTHREADS);
    dim3 grid(W / 128, (H / SH) / WPB, B);
    const int nblocks = grid.x * grid.y * grid.z;

    normal_loss_kernel<<<grid, block>>>(pred, gt, mask, out, H, W, nblocks);
}

// round 15
// speedup vs baseline: 2.7789x; 2.7789x over previous
#include <cuda_runtime.h>

#define TILE_W 128
#define TILE_H 16
#define HROWS  (TILE_H + 2)      // 18
#define NTHREADS 256
#define MAXB 8192

__device__ float2 g_part[MAXB];
__device__ unsigned int g_done = 0;   // self-resetting -> graph-replay safe

// Interior tile: aligned 128-col rows (STS.128 / LDS.128 conflict-free).
// Halo columns x0-1 / x0+128 live in side arrays.
struct Tile {
    float s[3][HROWS][TILE_W];
    float hl[3][HROWS];
    float hr[3][HROWS];
};

// Load one tensor (3ch x 18 rows x 128 cols + edges) into the tile.
// 54 row-tasks x 32 lanes = 1728 float4 tasks; 7 batched LDG.128/thread.
__device__ __forceinline__ void load_tile(
    Tile* T, const float* __restrict__ src0, int plane,
    int x0, int y0, int H, int W, int tid)
{
    float4 v[7];
    int    tc[7], tr[7], tl[7];
    #pragma unroll
    for (int k = 0; k < 7; k++) {
        int idx = tid + k * NTHREADS;            // < 1792; active if < 1728
        const bool act = (k < 6) || (tid < 192);
        int t = idx >> 5; if (t > 53) t = 53;
        const int l5 = idx & 31;
        const int ch = t / 18;
        const int r  = t - ch * 18;
        const int gy = y0 + r - 1;
        const bool inrow = act && (gy >= 0) && (gy < H);
        v[k] = make_float4(0.f, 0.f, 0.f, 0.f);
        if (inrow) v[k] = *(const float4*)(src0 + ch * plane + gy * W + x0 + 4 * l5);
        tc[k] = ch; tr[k] = r; tl[k] = l5;
    }
    // Edge columns: 54 rows x 2 sides = 108 scalar tasks.
    float ev = 0.f;
    int ech = 0, er = 0, eside = 0;
    const bool has_e = (tid < 108);
    if (has_e) {
        const int t = tid >> 1;
        eside = tid & 1;
        ech = t / 18;
        er  = t - ech * 18;
        const int gy = y0 + er - 1;
        const int gx = eside ? (x0 + TILE_W) : (x0 - 1);
        if (gy >= 0 && gy < H && gx >= 0 && gx < W)
            ev = src0[ech * plane + gy * W + gx];
    }
    #pragma unroll
    for (int k = 0; k < 7; k++) {
        if (k == 6 && tid >= 192) break;
        *(float4*)&T->s[tc[k]][tr[k]][4 * tl[k]] = v[k];   // aligned STS.128
    }
    if (has_e) {
        if (eside) T->hr[ech][er] = ev;
        else       T->hl[ech][er] = ev;
    }
}

// Gradients for two output rows (smem rows r0, r0+1); x-neighbors via shfl.
__device__ __forceinline__ void grads_2rows(
    const Tile* T, int r0, int tx,
    float GX0[3][4], float GY0[3][4], float GX1[3][4], float GY1[3][4])
{
    #pragma unroll
    for (int ch = 0; ch < 3; ch++) {
        float e[4][6];
        #pragma unroll
        for (int rr = 0; rr < 4; rr++) {
            const int row = r0 - 1 + rr;
            float4 v = *(const float4*)&T->s[ch][row][4 * tx];  // aligned LDS.128
            float L = __shfl_up_sync(0xFFFFFFFFu, v.w, 1);
            float R = __shfl_down_sync(0xFFFFFFFFu, v.x, 1);
            float hl = T->hl[ch][row];                          // broadcast LDS
            float hr = T->hr[ch][row];
            e[rr][0] = (tx == 0)  ? hl : L;
            e[rr][1] = v.x; e[rr][2] = v.y; e[rr][3] = v.z; e[rr][4] = v.w;
            e[rr][5] = (tx == 31) ? hr : R;
        }
        float cs0[6], rd0[6], cs1[6], rd1[6];
        #pragma unroll
        for (int j = 0; j < 6; j++) {
            const float bc = e[1][j] + e[2][j];
            cs0[j] = e[0][j] + bc;
            rd0[j] = e[2][j] - e[0][j];
            cs1[j] = bc + e[3][j];
            rd1[j] = e[3][j] - e[1][j];
        }
        #pragma unroll
        for (int i = 0; i < 4; i++) {
            GX0[ch][i] = cs0[i + 2] - cs0[i];
            GY0[ch][i] = rd0[i] + rd0[i + 1] + rd0[i + 2];
            GX1[ch][i] = cs1[i + 2] - cs1[i];
            GY1[ch][i] = rd1[i] + rd1[i + 1] + rd1[i + 2];
        }
    }
}

__device__ __forceinline__ void cross_norm(
    const float GX[3][4], const float GY[3][4],
    float* nxo, float* nyo, float* nzo)
{
    #pragma unroll
    for (int i = 0; i < 4; i++) {
        float nx = GX[1][i] * GY[2][i] - GX[2][i] * GY[1][i];
        float ny = GX[2][i] * GY[0][i] - GX[0][i] * GY[2][i];
        float nz = GX[0][i] * GY[1][i] - GX[1][i] * GY[0][i];
        float inv = rsqrtf(nx * nx + ny * ny + nz * nz + 1e-20f);
        nxo[i] = nx * inv; nyo[i] = ny * inv; nzo[i] = nz * inv;
    }
}

__global__ __launch_bounds__(NTHREADS, 3) void normal_loss_kernel(
    const float* __restrict__ pred,
    const float* __restrict__ gt,
    const float* __restrict__ mask,
    float* __restrict__ out,
    int H, int W, int nblocks)
{
    __shared__ Tile  T;                        // ~27.5 KB, reused for both tensors
    __shared__ float red_l[NTHREADS / 32];
    __shared__ float red_m[NTHREADS / 32];
    __shared__ double dred_l[NTHREADS / 32];
    __shared__ double dred_m[NTHREADS / 32];
    __shared__ int s_last;

    const int b  = blockIdx.z;
    const int x0 = blockIdx.x * TILE_W;
    const int y0 = blockIdx.y * TILE_H;
    const int tx = threadIdx.x;           // 0..31
    const int ty = threadIdx.y;           // 0..7  (== warp id)
    const int tid = ty * 32 + tx;
    const int warp = tid >> 5;
    const int lane = tid & 31;

    const int plane = H * W;
    const float* pb = pred + (size_t)b * 3 * plane;
    const float* gb = gt   + (size_t)b * 3 * plane;
    const float* mb = mask + (size_t)b * plane;

    const int r0 = 2 * ty + 1;            // smem row of first output row

    // ---- Phase P: pred ----
    load_tile(&T, pb, plane, x0, y0, H, W, tid);
    __syncthreads();

    float pnx[8], pny[8], pnz[8];
    {
        float GX0[3][4], GY0[3][4], GX1[3][4], GY1[3][4];
        grads_2rows(&T, r0, tx, GX0, GY0, GX1, GY1);
        cross_norm(GX0, GY0, &pnx[0], &pny[0], &pnz[0]);
        cross_norm(GX1, GY1, &pnx[4], &pny[4], &pnz[4]);
    }
    __syncthreads();

    // ---- Phase G: gt (reuse smem) ----
    load_tile(&T, gb, plane, x0, y0, H, W, tid);
    __syncthreads();

    float lsum = 0.f, msum = 0.f;
    {
        float GX0[3][4], GY0[3][4], GX1[3][4], GY1[3][4];
        grads_2rows(&T, r0, tx, GX0, GY0, GX1, GY1);
        float gnx[8], gny[8], gnz[8];
        cross_norm(GX0, GY0, &gnx[0], &gny[0], &gnz[0]);
        cross_norm(GX1, GY1, &gnx[4], &gny[4], &gnz[4]);

        const int py = y0 + 2 * ty;
        float4 m0 = *(const float4*)(mb + py * W + x0 + 4 * tx);
        float4 m1 = *(const float4*)(mb + (py + 1) * W + x0 + 4 * tx);
        float mm[8] = {m0.x, m0.y, m0.z, m0.w, m1.x, m1.y, m1.z, m1.w};
        #pragma unroll
        for (int i = 0; i < 8; i++) {
            lsum += mm[i] * (fabsf(pnx[i] - gnx[i]) + fabsf(pny[i] - gny[i])
                           + fabsf(pnz[i] - gnz[i]));
            msum += mm[i];
        }
    }

    // ---- Block reduction -> per-block partial ----
    #pragma unroll
    for (int o = 16; o > 0; o >>= 1) {
        lsum += __shfl_down_sync(0xFFFFFFFFu, lsum, o);
        msum += __shfl_down_sync(0xFFFFFFFFu, msum, o);
    }
    if (lane == 0) { red_l[warp] = lsum; red_m[warp] = msum; }
    __syncthreads();

    const int bid = (blockIdx.z * gridDim.y + blockIdx.y) * gridDim.x + blockIdx.x;
    if (tid == 0) {
        float tl = 0.f, tm = 0.f;
        #pragma unroll
        for (int w = 0; w < NTHREADS / 32; w++) { tl += red_l[w]; tm += red_m[w]; }
        g_part[bid] = make_float2(tl, tm);
        __threadfence();
        unsigned int old = atomicAdd(&g_done, 1u);
        s_last = (old == (unsigned)(nblocks - 1)) ? 1 : 0;
    }
    __syncthreads();

    // ---- Last block: final double-precision reduction + output + reset ----
    if (s_last) {
        double dl = 0.0, dm = 0.0;
        for (int i = tid; i < nblocks; i += NTHREADS) {
            float2 p = __ldcg(&g_part[i]);
            dl += (double)p.x; dm += (double)p.y;
        }
        #pragma unroll
        for (int o = 16; o > 0; o >>= 1) {
            dl += __shfl_down_sync(0xFFFFFFFFu, dl, o);
            dm += __shfl_down_sync(0xFFFFFFFFu, dm, o);
        }
        if (lane == 0) { dred_l[warp] = dl; dred_m[warp] = dm; }
        __syncthreads();
        if (tid == 0) {
            double tl = 0.0, tm = 0.0;
            #pragma unroll
            for (int w = 0; w < NTHREADS / 32; w++) { tl += dred_l[w]; tm += dred_m[w]; }
            out[0] = (float)(tl / tm);
            g_done = 0;   // restore for next graph replay
        }
    }
}

extern "C" void kernel_launch(void* const* d_in, const int* in_sizes, int n_in,
                              void* d_out, int out_size)
{
    const float* pred = (const float*)d_in[0];
    const float* gt   = (const float*)d_in[1];
    const float* mask = (const float*)d_in[2];
    float* out = (float*)d_out;

    const int H = 384;
    const int W = 1280;
    const int B = in_sizes[2] / (H * W);

    dim3 block(32, 8);
    dim3 grid(W / TILE_W, H / TILE_H, B);
    const int nblocks = grid.x * grid.y * grid.z;

    normal_loss_kernel<<<grid, block>>>(pred, gt, mask, out, H, W, nblocks);
}

// round 16
// speedup vs baseline: 2.8253x; 1.0167x over previous
#include <cuda_runtime.h>

#define TILE_W 128
#define TILE_H 16
#define HROWS  (TILE_H + 2)      // 18
#define ROWPAD 132               // cols: 0=left halo, 1..128 interior, 129 right halo
#define NTHREADS 256
#define MAXB 8192

__device__ float2 g_part[MAXB];
__device__ unsigned int g_done = 0;   // self-resetting -> graph-replay safe

// Load one tensor's 3 channels x 18 halo rows into s[3][HROWS][ROWPAD].
// 54 row-tasks x 32 lanes = 1728 float4 tasks; 7 batched independent LDG.128
// per thread (high MLP), scalar STS (interior col 1 start is not 16B aligned).
__device__ __forceinline__ void load_tile(
    float (*s)[HROWS][ROWPAD],
    const float* __restrict__ src0, int plane,
    int x0, int y0, int H, int W, int tid)
{
    float4 v[7];
    int   tt[7], rr[7], ll[7];
    #pragma unroll
    for (int k = 0; k < 7; k++) {
        int idx = tid + k * NTHREADS;            // < 1792; active if < 1728
        const bool act = (k < 6) || (tid < 192);
        int t  = idx >> 5; if (t > 53) t = 53;
        const int l5 = idx & 31;
        const int ch = t / 18;
        const int r  = t - ch * 18;
        const int gy = y0 + r - 1;
        const bool inrow = act && (gy >= 0) && (gy < H);
        v[k] = make_float4(0.f, 0.f, 0.f, 0.f);
        if (inrow) v[k] = *(const float4*)(src0 + ch * plane + gy * W + x0 + 4 * l5);
        tt[k] = ch; rr[k] = r; ll[k] = l5;
    }
    // Edge columns: 54 rows x 2 sides = 108 scalar tasks.
    float ev = 0.f;
    int ech = 0, er = 0, ecol = 0;
    bool has_e = (tid < 108);
    if (has_e) {
        const int t    = tid >> 1;
        const int side = tid & 1;
        ech = t / 18;
        er  = t - ech * 18;
        const int gy = y0 + er - 1;
        const int gx = side ? (x0 + TILE_W) : (x0 - 1);
        if (gy >= 0 && gy < H && gx >= 0 && gx < W)
            ev = src0[ech * plane + gy * W + gx];
        ecol = side ? (TILE_W + 1) : 0;
    }
    #pragma unroll
    for (int k = 0; k < 7; k++) {
        if (k == 6 && tid >= 192) break;
        float* p = &s[tt[k]][rr[k]][1 + 4 * ll[k]];
        p[0] = v[k].x; p[1] = v[k].y; p[2] = v[k].z; p[3] = v[k].w;
    }
    if (has_e) s[ech][er][ecol] = ev;
}

// Compute GX/GY for both output rows (r0, r0+1) of all 3 channels.
__device__ __forceinline__ void grads_2rows(
    const float (*s)[HROWS][ROWPAD], int r0, int c0,
    float GX0[3][4], float GY0[3][4], float GX1[3][4], float GY1[3][4])
{
    #pragma unroll
    for (int ch = 0; ch < 3; ch++) {
        float A[8], B[8], C[8], D[8];
        const float4* a4 = (const float4*)&s[ch][r0 - 1][c0];
        const float4* b4 = (const float4*)&s[ch][r0    ][c0];
        const float4* c4 = (const float4*)&s[ch][r0 + 1][c0];
        const float4* d4 = (const float4*)&s[ch][r0 + 2][c0];
        *(float4*)&A[0] = a4[0]; *(float4*)&A[4] = a4[1];
        *(float4*)&B[0] = b4[0]; *(float4*)&B[4] = b4[1];
        *(float4*)&C[0] = c4[0]; *(float4*)&C[4] = c4[1];
        *(float4*)&D[0] = d4[0]; *(float4*)&D[4] = d4[1];

        float cs0[6], rd0[6], cs1[6], rd1[6];
        #pragma unroll
        for (int j = 0; j < 6; j++) {
            const float bc = B[j] + C[j];
            cs0[j] = A[j] + bc;        // rows r0-1..r0+1
            rd0[j] = C[j] - A[j];
            cs1[j] = bc + D[j];        // rows r0..r0+2
            rd1[j] = D[j] - B[j];
        }
        #pragma unroll
        for (int i = 0; i < 4; i++) {
            GX0[ch][i] = cs0[i + 2] - cs0[i];
            GY0[ch][i] = rd0[i] + rd0[i + 1] + rd0[i + 2];
            GX1[ch][i] = cs1[i + 2] - cs1[i];
            GY1[ch][i] = rd1[i] + rd1[i + 1] + rd1[i + 2];
        }
    }
}

__device__ __forceinline__ void cross_norm(
    const float GX[3][4], const float GY[3][4],
    float* nxo, float* nyo, float* nzo)
{
    #pragma unroll
    for (int i = 0; i < 4; i++) {
        float nx = GX[1][i] * GY[2][i] - GX[2][i] * GY[1][i];
        float ny = GX[2][i] * GY[0][i] - GX[0][i] * GY[2][i];
        float nz = GX[0][i] * GY[1][i] - GX[1][i] * GY[0][i];
        float inv = rsqrtf(nx * nx + ny * ny + nz * nz + 1e-20f);
        nxo[i] = nx * inv; nyo[i] = ny * inv; nzo[i] = nz * inv;
    }
}

__global__ __launch_bounds__(NTHREADS, 4) void normal_loss_kernel(
    const float* __restrict__ pred,
    const float* __restrict__ gt,
    const float* __restrict__ mask,
    float* __restrict__ out,
    int H, int W, int nblocks)
{
    __shared__ float s[3][HROWS][ROWPAD];        // 28.5 KB, reused for both tensors
    __shared__ float red_l[NTHREADS / 32];
    __shared__ float red_m[NTHREADS / 32];
    __shared__ double dred_l[NTHREADS / 32];
    __shared__ double dred_m[NTHREADS / 32];
    __shared__ int s_last;

    const int b  = blockIdx.z;
    const int x0 = blockIdx.x * TILE_W;
    const int y0 = blockIdx.y * TILE_H;
    const int tx = threadIdx.x;           // 0..31
    const int ty = threadIdx.y;           // 0..7
    const int tid = ty * 32 + tx;
    const int warp = tid >> 5;
    const int lane = tid & 31;

    const int plane = H * W;
    const float* pb = pred + (size_t)b * 3 * plane;
    const float* gb = gt   + (size_t)b * 3 * plane;
    const float* mb = mask + (size_t)b * plane;

    const int r0 = 2 * ty + 1;            // smem row of first output row
    const int c0 = 4 * tx;                // 16B-aligned

    // ---- Phase P: pred ----
    load_tile(s, pb, plane, x0, y0, H, W, tid);
    __syncthreads();

    float pnx[8], pny[8], pnz[8];
    {
        float GX0[3][4], GY0[3][4], GX1[3][4], GY1[3][4];
        grads_2rows(s, r0, c0, GX0, GY0, GX1, GY1);
        cross_norm(GX0, GY0, &pnx[0], &pny[0], &pnz[0]);
        cross_norm(GX1, GY1, &pnx[4], &pny[4], &pnz[4]);
    }
    __syncthreads();

    // ---- Phase G: gt (reuse smem) ----
    load_tile(s, gb, plane, x0, y0, H, W, tid);
    __syncthreads();

    float lsum = 0.f, msum = 0.f;
    {
        float GX0[3][4], GY0[3][4], GX1[3][4], GY1[3][4];
        grads_2rows(s, r0, c0, GX0, GY0, GX1, GY1);
        float gnx[8], gny[8], gnz[8];
        cross_norm(GX0, GY0, &gnx[0], &gny[0], &gnz[0]);
        cross_norm(GX1, GY1, &gnx[4], &gny[4], &gnz[4]);

        const int py = y0 + 2 * ty;
        float4 m0 = *(const float4*)(mb + py * W + x0 + c0);
        float4 m1 = *(const float4*)(mb + (py + 1) * W + x0 + c0);
        float mm[8] = {m0.x, m0.y, m0.z, m0.w, m1.x, m1.y, m1.z, m1.w};
        #pragma unroll
        for (int i = 0; i < 8; i++) {
            lsum += mm[i] * (fabsf(pnx[i] - gnx[i]) + fabsf(pny[i] - gny[i])
                           + fabsf(pnz[i] - gnz[i]));
            msum += mm[i];
        }
    }

    // ---- Block reduction -> per-block partial ----
    #pragma unroll
    for (int o = 16; o > 0; o >>= 1) {
        lsum += __shfl_down_sync(0xFFFFFFFFu, lsum, o);
        msum += __shfl_down_sync(0xFFFFFFFFu, msum, o);
    }
    if (lane == 0) { red_l[warp] = lsum; red_m[warp] = msum; }
    __syncthreads();

    const int bid = (blockIdx.z * gridDim.y + blockIdx.y) * gridDim.x + blockIdx.x;
    if (tid == 0) {
        float tl = 0.f, tm = 0.f;
        #pragma unroll
        for (int w = 0; w < NTHREADS / 32; w++) { tl += red_l[w]; tm += red_m[w]; }
        g_part[bid] = make_float2(tl, tm);
        __threadfence();
        unsigned int old = atomicAdd(&g_done, 1u);
        s_last = (old == (unsigned)(nblocks - 1)) ? 1 : 0;
    }
    __syncthreads();

    // ---- Last block: final reduction + output + counter reset ----
    if (s_last) {
        double dl = 0.0, dm = 0.0;
        for (int i = tid; i < nblocks; i += NTHREADS) {
            float2 p = __ldcg(&g_part[i]);
            dl += (double)p.x; dm += (double)p.y;
        }
        #pragma unroll
        for (int o = 16; o > 0; o >>= 1) {
            dl += __shfl_down_sync(0xFFFFFFFFu, dl, o);
            dm += __shfl_down_sync(0xFFFFFFFFu, dm, o);
        }
        if (lane == 0) { dred_l[warp] = dl; dred_m[warp] = dm; }
        __syncthreads();
        if (tid == 0) {
            double tl = 0.0, tm = 0.0;
            #pragma unroll
            for (int w = 0; w < NTHREADS / 32; w++) { tl += dred_l[w]; tm += dred_m[w]; }
            out[0] = (float)(tl / tm);
            g_done = 0;   // restore for next graph replay
        }
    }
}

extern "C" void kernel_launch(void* const* d_in, const int* in_sizes, int n_in,
                              void* d_out, int out_size)
{
    const float* pred = (const float*)d_in[0];
    const float* gt   = (const float*)d_in[1];
    const float* mask = (const float*)d_in[2];
    float* out = (float*)d_out;

    const int H = 384;
    const int W = 1280;
    const int B = in_sizes[2] / (H * W);

    dim3 block(32, 8);
    dim3 grid(W / TILE_W, H / TILE_H, B);
    const int nblocks = grid.x * grid.y * grid.z;

    normal_loss_kernel<<<grid, block>>>(pred, gt, mask, out, H, W, nblocks);
}

// round 17
// speedup vs baseline: 2.9742x; 1.0527x over previous
#include <cuda_runtime.h>

#define TILE_W 128
#define TILE_H 16
#define HROWS  (TILE_H + 2)      // 18
#define ROWPAD 132               // cols: 0=left halo, 1..128 interior, 129 right halo
#define NTHREADS 256
#define MAXB 8192

__device__ float2 g_part[MAXB];
__device__ unsigned int g_done = 0;   // self-resetting -> graph-replay safe

struct Smem {
    float s[2][3][HROWS][ROWPAD];    // 57,024 B: both tensors resident
    float red_l[NTHREADS / 32];
    float red_m[NTHREADS / 32];
    double dred_l[NTHREADS / 32];
    double dred_m[NTHREADS / 32];
    int s_last;
};
#define SMEM_BYTES sizeof(Smem)

// Load one tensor's 3 channels x 18 halo rows into s[3][HROWS][ROWPAD].
// 54 row-tasks x 32 lanes = 1728 float4 tasks; 7 batched independent LDG.128
// per thread (high MLP), scalar STS (interior col 1 start is not 16B aligned).
__device__ __forceinline__ void load_tile(
    float (*s)[HROWS][ROWPAD],
    const float* __restrict__ src0, int plane,
    int x0, int y0, int H, int W, int tid)
{
    float4 v[7];
    int   tt[7], rr[7], ll[7];
    #pragma unroll
    for (int k = 0; k < 7; k++) {
        int idx = tid + k * NTHREADS;            // < 1792; active if < 1728
        const bool act = (k < 6) || (tid < 192);
        int t  = idx >> 5; if (t > 53) t = 53;
        const int l5 = idx & 31;
        const int ch = t / 18;
        const int r  = t - ch * 18;
        const int gy = y0 + r - 1;
        const bool inrow = act && (gy >= 0) && (gy < H);
        v[k] = make_float4(0.f, 0.f, 0.f, 0.f);
        if (inrow) v[k] = *(const float4*)(src0 + ch * plane + gy * W + x0 + 4 * l5);
        tt[k] = ch; rr[k] = r; ll[k] = l5;
    }
    // Edge columns: 54 rows x 2 sides = 108 scalar tasks.
    float ev = 0.f;
    int ech = 0, er = 0, ecol = 0;
    bool has_e = (tid < 108);
    if (has_e) {
        const int t    = tid >> 1;
        const int side = tid & 1;
        ech = t / 18;
        er  = t - ech * 18;
        const int gy = y0 + er - 1;
        const int gx = side ? (x0 + TILE_W) : (x0 - 1);
        if (gy >= 0 && gy < H && gx >= 0 && gx < W)
            ev = src0[ech * plane + gy * W + gx];
        ecol = side ? (TILE_W + 1) : 0;
    }
    #pragma unroll
    for (int k = 0; k < 7; k++) {
        if (k == 6 && tid >= 192) break;
        float* p = &s[tt[k]][rr[k]][1 + 4 * ll[k]];
        p[0] = v[k].x; p[1] = v[k].y; p[2] = v[k].z; p[3] = v[k].w;
    }
    if (has_e) s[ech][er][ecol] = ev;
}

// Compute GX/GY for both output rows (r0, r0+1) of all 3 channels.
__device__ __forceinline__ void grads_2rows(
    const float (*s)[HROWS][ROWPAD], int r0, int c0,
    float GX0[3][4], float GY0[3][4], float GX1[3][4], float GY1[3][4])
{
    #pragma unroll
    for (int ch = 0; ch < 3; ch++) {
        float A[8], B[8], C[8], D[8];
        const float4* a4 = (const float4*)&s[ch][r0 - 1][c0];
        const float4* b4 = (const float4*)&s[ch][r0    ][c0];
        const float4* c4 = (const float4*)&s[ch][r0 + 1][c0];
        const float4* d4 = (const float4*)&s[ch][r0 + 2][c0];
        *(float4*)&A[0] = a4[0]; *(float4*)&A[4] = a4[1];
        *(float4*)&B[0] = b4[0]; *(float4*)&B[4] = b4[1];
        *(float4*)&C[0] = c4[0]; *(float4*)&C[4] = c4[1];
        *(float4*)&D[0] = d4[0]; *(float4*)&D[4] = d4[1];

        float cs0[6], rd0[6], cs1[6], rd1[6];
        #pragma unroll
        for (int j = 0; j < 6; j++) {
            const float bc = B[j] + C[j];
            cs0[j] = A[j] + bc;        // rows r0-1..r0+1
            rd0[j] = C[j] - A[j];
            cs1[j] = bc + D[j];        // rows r0..r0+2
            rd1[j] = D[j] - B[j];
        }
        #pragma unroll
        for (int i = 0; i < 4; i++) {
            GX0[ch][i] = cs0[i + 2] - cs0[i];
            GY0[ch][i] = rd0[i] + rd0[i + 1] + rd0[i + 2];
            GX1[ch][i] = cs1[i + 2] - cs1[i];
            GY1[ch][i] = rd1[i] + rd1[i + 1] + rd1[i + 2];
        }
    }
}

__device__ __forceinline__ void cross_norm(
    const float GX[3][4], const float GY[3][4],
    float* nxo, float* nyo, float* nzo)
{
    #pragma unroll
    for (int i = 0; i < 4; i++) {
        float nx = GX[1][i] * GY[2][i] - GX[2][i] * GY[1][i];
        float ny = GX[2][i] * GY[0][i] - GX[0][i] * GY[2][i];
        float nz = GX[0][i] * GY[1][i] - GX[1][i] * GY[0][i];
        float inv = rsqrtf(nx * nx + ny * ny + nz * nz + 1e-20f);
        nxo[i] = nx * inv; nyo[i] = ny * inv; nzo[i] = nz * inv;
    }
}

__global__ __launch_bounds__(NTHREADS, 3) void normal_loss_kernel(
    const float* __restrict__ pred,
    const float* __restrict__ gt,
    const float* __restrict__ mask,
    float* __restrict__ out,
    int H, int W, int nblocks)
{
    extern __shared__ char dynbuf[];
    Smem* SM = (Smem*)dynbuf;

    const int b  = blockIdx.z;
    const int x0 = blockIdx.x * TILE_W;
    const int y0 = blockIdx.y * TILE_H;
    const int tx = threadIdx.x;           // 0..31
    const int ty = threadIdx.y;           // 0..7
    const int tid = ty * 32 + tx;
    const int warp = tid >> 5;
    const int lane = tid & 31;

    const int plane = H * W;
    const float* pb = pred + (size_t)b * 3 * plane;
    const float* gb = gt   + (size_t)b * 3 * plane;
    const float* mb = mask + (size_t)b * plane;

    const int r0 = 2 * ty + 1;            // smem row of first output row
    const int c0 = 4 * tx;                // 16B-aligned

    // ---- Single load phase: both tensors + mask, ONE barrier ----
    load_tile(SM->s[0], pb, plane, x0, y0, H, W, tid);
    load_tile(SM->s[1], gb, plane, x0, y0, H, W, tid);

    const int py = y0 + 2 * ty;
    float4 m0 = *(const float4*)(mb + py * W + x0 + c0);
    float4 m1 = *(const float4*)(mb + (py + 1) * W + x0 + c0);

    __syncthreads();

    // ---- Compute: pred normals, then gt + loss ----
    float pnx[8], pny[8], pnz[8];
    {
        float GX0[3][4], GY0[3][4], GX1[3][4], GY1[3][4];
        grads_2rows(SM->s[0], r0, c0, GX0, GY0, GX1, GY1);
        cross_norm(GX0, GY0, &pnx[0], &pny[0], &pnz[0]);
        cross_norm(GX1, GY1, &pnx[4], &pny[4], &pnz[4]);
    }

    float lsum = 0.f, msum = 0.f;
    {
        float GX0[3][4], GY0[3][4], GX1[3][4], GY1[3][4];
        grads_2rows(SM->s[1], r0, c0, GX0, GY0, GX1, GY1);
        float gnx[8], gny[8], gnz[8];
        cross_norm(GX0, GY0, &gnx[0], &gny[0], &gnz[0]);
        cross_norm(GX1, GY1, &gnx[4], &gny[4], &gnz[4]);

        float mm[8] = {m0.x, m0.y, m0.z, m0.w, m1.x, m1.y, m1.z, m1.w};
        #pragma unroll
        for (int i = 0; i < 8; i++) {
            lsum += mm[i] * (fabsf(pnx[i] - gnx[i]) + fabsf(pny[i] - gny[i])
                           + fabsf(pnz[i] - gnz[i]));
            msum += mm[i];
        }
    }

    // ---- Block reduction -> per-block partial ----
    #pragma unroll
    for (int o = 16; o > 0; o >>= 1) {
        lsum += __shfl_down_sync(0xFFFFFFFFu, lsum, o);
        msum += __shfl_down_sync(0xFFFFFFFFu, msum, o);
    }
    if (lane == 0) { SM->red_l[warp] = lsum; SM->red_m[warp] = msum; }
    __syncthreads();

    const int bid = (blockIdx.z * gridDim.y + blockIdx.y) * gridDim.x + blockIdx.x;
    if (tid == 0) {
        float tl = 0.f, tm = 0.f;
        #pragma unroll
        for (int w = 0; w < NTHREADS / 32; w++) { tl += SM->red_l[w]; tm += SM->red_m[w]; }
        g_part[bid] = make_float2(tl, tm);
        __threadfence();
        unsigned int old = atomicAdd(&g_done, 1u);
        SM->s_last = (old == (unsigned)(nblocks - 1)) ? 1 : 0;
    }
    __syncthreads();

    // ---- Last block: final reduction + output + counter reset ----
    if (SM->s_last) {
        double dl = 0.0, dm = 0.0;
        for (int i = tid; i < nblocks; i += NTHREADS) {
            float2 p = __ldcg(&g_part[i]);
            dl += (double)p.x; dm += (double)p.y;
        }
        #pragma unroll
        for (int o = 16; o > 0; o >>= 1) {
            dl += __shfl_down_sync(0xFFFFFFFFu, dl, o);
            dm += __shfl_down_sync(0xFFFFFFFFu, dm, o);
        }
        if (lane == 0) { SM->dred_l[warp] = dl; SM->dred_m[warp] = dm; }
        __syncthreads();
        if (tid == 0) {
            double tl = 0.0, tm = 0.0;
            #pragma unroll
            for (int w = 0; w < NTHREADS / 32; w++) { tl += SM->dred_l[w]; tm += SM->dred_m[w]; }
            out[0] = (float)(tl / tm);
            g_done = 0;   // restore for next graph replay
        }
    }
}

extern "C" void kernel_launch(void* const* d_in, const int* in_sizes, int n_in,
                              void* d_out, int out_size)
{
    const float* pred = (const float*)d_in[0];
    const float* gt   = (const float*)d_in[1];
    const float* mask = (const float*)d_in[2];
    float* out = (float*)d_out;

    const int H = 384;
    const int W = 1280;
    const int B = in_sizes[2] / (H * W);

    // >48KB smem requires opting in (host-side, idempotent, capture-legal).
    cudaFuncSetAttribute(normal_loss_kernel,
                         cudaFuncAttributeMaxDynamicSharedMemorySize,
                         (int)SMEM_BYTES);

    dim3 block(32, 8);
    dim3 grid(W / TILE_W, H / TILE_H, B);
    const int nblocks = grid.x * grid.y * grid.z;

    normal_loss_kernel<<<grid, block, SMEM_BYTES>>>(pred, gt, mask, out, H, W, nblocks);
}